// round 1
// baseline (speedup 1.0000x reference)
#include <cuda_runtime.h>
#include <cuda_bf16.h>

// Inputs (metadata order):
//   d_in[0] x                    float32 [2048]
//   d_in[1] y                    float32 [2048]
//   d_in[2] post_order_expression int32  [15]
//   d_in[3] post_level_map        int32  [15]
//   d_in[4] is_operator           bool   [5]   (not read; op semantics: v>=3 => operator)
//   d_in[5] parameters            float32 [15,3]
// Output: float32 [2048, 2048] row-major, out[i*D2 + j] = K(x[i], y[j])

#define NUM_ATOMS 3
#define MAX_NODES 15
#define EPSX 1e-6f
#define LOG2E 1.4426950408889634f

// Compiled program (active nodes only), produced by compile_kernel.
__device__ int    g_nprog;
__device__ int    g_op[MAX_NODES];
__device__ float4 g_c[MAX_NODES];

// ---------------------------------------------------------------------------
// Pre-kernel: fold the tree into a compact program with derived constants.
// Runs once, 1 thread; cost is noise. Keeps all RCP/division work out of the
// per-element path.
//   atom 0 (rbf):      k = c0 * exp2(c1 * dx*dx)         c0=p0^2, c1=-0.5*log2e/(p1^2+eps)
//   atom 1 (linear):   k = fma(c0, x*y, c1)              c0=p0^2, c1=p1^2
//   atom 2 (periodic): k = c0 * exp2(c1 * sinpi(dx*c2)^2) c0=p0^2, c1=-2*log2e/(p1^2+eps), c2=1/(p2^2+1)
//   op 3: add, op 4: mul  (both commutative, so l/r order is irrelevant)
// ---------------------------------------------------------------------------
__global__ void tree_compile_kernel(const int* __restrict__ post_expr,
                                    const int* __restrict__ post_level,
                                    const float* __restrict__ params) {
    if (threadIdx.x != 0 || blockIdx.x != 0) return;
    int na = 0;
    for (int i = 0; i < MAX_NODES; ++i) {
        int v = post_expr[i];
        if (v < 0) continue;
        float4 c = make_float4(0.f, 0.f, 0.f, 0.f);
        if (v < NUM_ATOMS) {
            int lvl = post_level[i];
            float p0 = params[3 * lvl + 0];
            float p1 = params[3 * lvl + 1];
            float p2 = params[3 * lvl + 2];
            float p0s = p0 * p0;
            float p1s = p1 * p1;
            if (v == 0) {                 // rbf
                c.x = p0s;
                c.y = -0.5f * LOG2E / (p1s + EPSX);
            } else if (v == 1) {          // linear
                c.x = p0s;
                c.y = p1s;
            } else {                      // periodic
                c.x = p0s;
                c.y = -2.0f * LOG2E / (p1s + EPSX);
                c.z = 1.0f / (p2 * p2 + 1.0f);
            }
        }
        g_op[na] = v;
        g_c[na]  = c;
        ++na;
    }
    g_nprog = na;
}

// ---------------------------------------------------------------------------
// Eval kernel: one thread computes a 1x4 strip out[i, 4*jq .. 4*jq+3].
// The stack program is identical for all threads -> all interpreter branches
// are warp-uniform. Stack is a tiny local array (4 slots x 4 lanes); the
// handful of LDL/STL.128 per thread is negligible at the LSU floor.
// ---------------------------------------------------------------------------
__global__ void __launch_bounds__(256)
tree_eval_kernel(const float* __restrict__ x,
                 const float* __restrict__ y,
                 float* __restrict__ out,
                 int d1, int d2) {
    __shared__ int    s_n;
    __shared__ int    s_op[MAX_NODES];
    __shared__ float4 s_c[MAX_NODES];
    if (threadIdx.x == 0) s_n = g_nprog;
    if (threadIdx.x < MAX_NODES) {
        s_op[threadIdx.x] = g_op[threadIdx.x];
        s_c[threadIdx.x]  = g_c[threadIdx.x];
    }
    __syncthreads();

    const int  qcols = d2 >> 2;                       // float4 columns
    const long total = (long)d1 * (long)qcols;
    const long idx   = (long)blockIdx.x * blockDim.x + threadIdx.x;
    if (idx >= total) return;

    const int i  = (int)(idx / qcols);
    const int jq = (int)(idx - (long)i * qcols);

    const float  xi = x[i];
    const float4 y4 = reinterpret_cast<const float4*>(y)[jq];
    float yv[4] = {y4.x, y4.y, y4.z, y4.w};
    float dx[4];
#pragma unroll
    for (int l = 0; l < 4; ++l) dx[l] = xi - yv[l];

    float st[4][4];
#pragma unroll
    for (int l = 0; l < 4; ++l) st[0][l] = 0.0f;      // empty-tree semantics
    int ptr = 0;

    const int n = s_n;
    for (int nn = 0; nn < n; ++nn) {
        const int    op = s_op[nn];
        const float4 c  = s_c[nn];
        if (op >= NUM_ATOMS) {
            // operator: l = st[ptr-1], r = st[ptr-2]; result -> st[ptr-2]
            if (op == NUM_ATOMS) {        // add
#pragma unroll
                for (int l = 0; l < 4; ++l)
                    st[ptr - 2][l] = st[ptr - 1][l] + st[ptr - 2][l];
            } else {                      // mul
#pragma unroll
                for (int l = 0; l < 4; ++l)
                    st[ptr - 2][l] = st[ptr - 1][l] * st[ptr - 2][l];
            }
            --ptr;
        } else if (op == 0) {             // rbf
#pragma unroll
            for (int l = 0; l < 4; ++l)
                st[ptr][l] = c.x * exp2f(c.y * dx[l] * dx[l]);
            ++ptr;
        } else if (op == 1) {             // linear
#pragma unroll
            for (int l = 0; l < 4; ++l)
                st[ptr][l] = fmaf(c.x, xi * yv[l], c.y);
            ++ptr;
        } else {                          // periodic
#pragma unroll
            for (int l = 0; l < 4; ++l) {
                float sp = sinpif(dx[l] * c.z);
                st[ptr][l] = c.x * exp2f(c.y * sp * sp);
            }
            ++ptr;
        }
    }

    float4 o;
    o.x = st[0][0]; o.y = st[0][1]; o.z = st[0][2]; o.w = st[0][3];
    reinterpret_cast<float4*>(out)[idx] = o;
}

extern "C" void kernel_launch(void* const* d_in, const int* in_sizes, int n_in,
                              void* d_out, int out_size) {
    const float* x      = (const float*)d_in[0];
    const float* y      = (const float*)d_in[1];
    const int*   pe     = (const int*)d_in[2];
    const int*   pl     = (const int*)d_in[3];
    const float* params = (const float*)d_in[5];
    float*       out    = (float*)d_out;

    const int d1 = in_sizes[0];
    const int d2 = in_sizes[1];

    tree_compile_kernel<<<1, 1>>>(pe, pl, params);

    const int  qcols   = d2 >> 2;                     // d2 == 2048, divisible by 4
    const long total   = (long)d1 * (long)qcols;
    const int  threads = 256;
    const int  blocks  = (int)((total + threads - 1) / threads);
    tree_eval_kernel<<<blocks, threads>>>(x, y, out, d1, d2);
}

// round 2
// speedup vs baseline: 1.8272x; 1.8272x over previous
#include <cuda_runtime.h>
#include <cuda_bf16.h>

// Inputs (metadata order):
//   d_in[0] x                     float32 [2048]
//   d_in[1] y                     float32 [2048]
//   d_in[2] post_order_expression int32   [15]
//   d_in[3] post_level_map        int32   [15]
//   d_in[4] is_operator           bool    [5]
//   d_in[5] parameters            float32 [15,3]
// Output: float32 [D1, D2] row-major, out[i*D2 + j] = K(x[i], y[j])

#define NUM_ATOMS 3
#define MAX_NODES 15
#define EPSX 1e-6f
#define LOG2E 1.4426950408889634f
#define TWO_PI 6.283185307179586f

// Compiled program (active nodes only).
__device__ int    g_nprog;
__device__ int    g_fast;              // 1 if program == [0,1,4,2,0,3,3]
__device__ int    g_op[MAX_NODES];
__device__ float4 g_c[MAX_NODES];

// ---------------------------------------------------------------------------
// Compile: fold tree into compact program + derived constants, detect the
// known shape for the register fast path.
//   rbf:      k = c0 * exp2(c1 * dx*dx)            c0=p0^2, c1=-0.5*log2e/(p1^2+eps)
//   linear:   k = fma(c0, x*y, c1)                 c0=p0^2, c1=p1^2
//   periodic: k = c0 * exp2(c1 * s^2),
//             s = sin(2*pi*frac) with h=dx*c2h, frac=h-rint(h), c2h=0.5/(p2^2+1)
//             c0=p0^2, c1=-2*log2e/(p1^2+eps)
// ---------------------------------------------------------------------------
__global__ void tree_compile_kernel(const int* __restrict__ post_expr,
                                    const int* __restrict__ post_level,
                                    const float* __restrict__ params) {
    if (threadIdx.x != 0 || blockIdx.x != 0) return;
    int na = 0;
    for (int i = 0; i < MAX_NODES; ++i) {
        int v = post_expr[i];
        if (v < 0) continue;
        float4 c = make_float4(0.f, 0.f, 0.f, 0.f);
        if (v < NUM_ATOMS) {
            int lvl = post_level[i];
            float p0 = params[3 * lvl + 0];
            float p1 = params[3 * lvl + 1];
            float p2 = params[3 * lvl + 2];
            float p0s = p0 * p0;
            float p1s = p1 * p1;
            if (v == 0) {                 // rbf
                c.x = p0s;
                c.y = -0.5f * LOG2E / (p1s + EPSX);
            } else if (v == 1) {          // linear
                c.x = p0s;
                c.y = p1s;
            } else {                      // periodic
                c.x = p0s;
                c.y = -2.0f * LOG2E / (p1s + EPSX);
                c.z = 0.5f / (p2 * p2 + 1.0f);   // half-period scale
            }
        }
        g_op[na] = v;
        g_c[na]  = c;
        ++na;
    }
    g_nprog = na;
    // Fast-path fingerprint: rbf, lin, mul, per, rbf, add, add
    const int want[7] = {0, 1, 4, 2, 0, 3, 3};
    int fast = (na == 7);
    for (int i = 0; i < 7 && fast; ++i) fast = (g_op[i] == want[i]);
    g_fast = fast;
}

__device__ __forceinline__ float sin2pi_frac(float h) {
    // h = dx * (0.5 * c2). Returns sin(2*pi*(h - rint(h))), |arg| <= pi.
    float f = h - rintf(h);
    return __sinf(TWO_PI * f);
}

// ---------------------------------------------------------------------------
// Eval: one block per output row, one float4 of y per thread.
// Fast path: fully unrolled, stack in registers, dx*dx reused.
// Generic path: warp-uniform interpreter (local stack) — correctness fallback.
// ---------------------------------------------------------------------------
__global__ void __launch_bounds__(512)
tree_eval_kernel(const float* __restrict__ x,
                 const float* __restrict__ y,
                 float* __restrict__ out,
                 int d2) {
    const int i = blockIdx.x;
    const int t = threadIdx.x;
    const int qcols = d2 >> 2;
    if (t >= qcols) return;

    const float  xi = __ldg(x + i);
    const float4 y4 = __ldg(reinterpret_cast<const float4*>(y) + t);
    float yv[4] = {y4.x, y4.y, y4.z, y4.w};
    float dx[4];
#pragma unroll
    for (int l = 0; l < 4; ++l) dx[l] = xi - yv[l];

    float4 o;
    float* res = &o.x;

    if (g_fast) {
        const float4 cA = g_c[0];   // rbf
        const float4 cB = g_c[1];   // linear
        const float4 cP = g_c[3];   // periodic
        const float4 cD = g_c[4];   // rbf
#pragma unroll
        for (int l = 0; l < 4; ++l) {
            float d  = dx[l];
            float d2s = d * d;
            float k1 = cA.x * exp2f(cA.y * d2s);          // rbf #1
            float k2 = fmaf(cB.x, xi * yv[l], cB.y);      // linear
            float m  = k1 * k2;                           // mul
            float s  = sin2pi_frac(d * cP.z);             // periodic
            float k3 = cP.x * exp2f(cP.y * s * s);
            float k4 = cD.x * exp2f(cD.y * d2s);          // rbf #2 (reuse d^2)
            res[l] = (k4 + k3) + m;                       // add, add
        }
    } else {
        // Generic interpreter fallback (uniform branches, tiny local stack).
        float st[4][4];
#pragma unroll
        for (int l = 0; l < 4; ++l) st[0][l] = 0.0f;
        int ptr = 0;
        const int n = g_nprog;
        for (int nn = 0; nn < n; ++nn) {
            const int    op = g_op[nn];
            const float4 c  = g_c[nn];
            if (op >= NUM_ATOMS) {
                if (op == NUM_ATOMS) {
#pragma unroll
                    for (int l = 0; l < 4; ++l)
                        st[ptr - 2][l] = st[ptr - 1][l] + st[ptr - 2][l];
                } else {
#pragma unroll
                    for (int l = 0; l < 4; ++l)
                        st[ptr - 2][l] = st[ptr - 1][l] * st[ptr - 2][l];
                }
                --ptr;
            } else if (op == 0) {
#pragma unroll
                for (int l = 0; l < 4; ++l)
                    st[ptr][l] = c.x * exp2f(c.y * dx[l] * dx[l]);
                ++ptr;
            } else if (op == 1) {
#pragma unroll
                for (int l = 0; l < 4; ++l)
                    st[ptr][l] = fmaf(c.x, xi * yv[l], c.y);
                ++ptr;
            } else {
#pragma unroll
                for (int l = 0; l < 4; ++l) {
                    float s = sin2pi_frac(dx[l] * c.z);
                    st[ptr][l] = c.x * exp2f(c.y * s * s);
                }
                ++ptr;
            }
        }
#pragma unroll
        for (int l = 0; l < 4; ++l) res[l] = st[0][l];
    }

    reinterpret_cast<float4*>(out + (size_t)i * d2)[t] = o;
}

// Scalar fallback for d2 not divisible by 4 (not expected in this bench).
__global__ void tree_eval_scalar_kernel(const float* __restrict__ x,
                                        const float* __restrict__ y,
                                        float* __restrict__ out,
                                        int d1, int d2) {
    long idx = (long)blockIdx.x * blockDim.x + threadIdx.x;
    long total = (long)d1 * d2;
    if (idx >= total) return;
    int i = (int)(idx / d2);
    int j = (int)(idx - (long)i * d2);
    float xi = x[i], yj = y[j];
    float dx = xi - yj;
    float st[4] = {0.f, 0.f, 0.f, 0.f};
    int ptr = 0;
    const int n = g_nprog;
    for (int nn = 0; nn < n; ++nn) {
        const int    op = g_op[nn];
        const float4 c  = g_c[nn];
        if (op >= NUM_ATOMS) {
            float v = (op == NUM_ATOMS) ? (st[ptr - 1] + st[ptr - 2])
                                        : (st[ptr - 1] * st[ptr - 2]);
            st[ptr - 2] = v; --ptr;
        } else if (op == 0) {
            st[ptr++] = c.x * exp2f(c.y * dx * dx);
        } else if (op == 1) {
            st[ptr++] = fmaf(c.x, xi * yj, c.y);
        } else {
            float s = sin2pi_frac(dx * c.z);
            st[ptr++] = c.x * exp2f(c.y * s * s);
        }
    }
    out[idx] = st[0];
}

extern "C" void kernel_launch(void* const* d_in, const int* in_sizes, int n_in,
                              void* d_out, int out_size) {
    const float* x      = (const float*)d_in[0];
    const float* y      = (const float*)d_in[1];
    const int*   pe     = (const int*)d_in[2];
    const int*   pl     = (const int*)d_in[3];
    const float* params = (const float*)d_in[5];
    float*       out    = (float*)d_out;

    const int d1 = in_sizes[0];
    const int d2 = in_sizes[1];

    tree_compile_kernel<<<1, 1>>>(pe, pl, params);

    if ((d2 & 3) == 0 && (d2 >> 2) <= 512) {
        tree_eval_kernel<<<d1, (d2 >> 2)>>>(x, y, out, d2);
    } else {
        long total = (long)d1 * d2;
        int blocks = (int)((total + 255) / 256);
        tree_eval_scalar_kernel<<<blocks, 256>>>(x, y, out, d1, d2);
    }
}